// round 1
// baseline (speedup 1.0000x reference)
#include <cuda_runtime.h>
#include <cstddef>

// Problem constants (fixed shapes from reference)
#define NTOK 4096   // H*W
#define DQK  64     // INTER
#define CVCH 256    // CS (v / output channels)
#define NB   4      // batch
#define TI   32     // query tile per block
#define TJ   64     // key tile per iteration

// Scratch for q/k/v projections (no cudaMalloc allowed)
__device__ float g_q[NB * DQK * NTOK];   // [b][d][n]
__device__ float g_k[NB * DQK * NTOK];   // [b][d][n]
__device__ float g_v[NB * CVCH * NTOK];  // [b][c][n]

__device__ __forceinline__ float fast_exp2(float x) {
    float r;
    asm("ex2.approx.ftz.f32 %0, %1;" : "=f"(r) : "f"(x));
    return r;
}

// ---------------------------------------------------------------------------
// Stage 1: 1x1 conv == GEMM  Y[b,o,n] = scale * (bias[o] + sum_c W[o,c] X[b,c,n])
// O = gridDim.y * 64. Tiled 64o x 64n, K-step 16, 4x4 per thread.
// ---------------------------------------------------------------------------
__global__ __launch_bounds__(256)
void conv1x1_kernel(const float* __restrict__ X, const float* __restrict__ W,
                    const float* __restrict__ bias, float* __restrict__ Y,
                    int C, float scale) {
    __shared__ float Ws[64][17];   // [o][k], pad 17 -> conflict-free
    __shared__ float Xs[16][64];   // [k][n]
    const int b  = blockIdx.z;
    const int O  = gridDim.y << 6;
    const int o0 = blockIdx.y << 6;
    const int n0 = blockIdx.x << 6;
    const int tid = threadIdx.x;
    const int tx = tid & 15;   // n quad
    const int ty = tid >> 4;   // o quad
    float acc[4][4];
    #pragma unroll
    for (int a = 0; a < 4; a++)
        #pragma unroll
        for (int c = 0; c < 4; c++) acc[a][c] = 0.f;

    const float* Xb = X + ((size_t)b * C) * NTOK + n0;
    for (int c0 = 0; c0 < C; c0 += 16) {
        __syncthreads();
        #pragma unroll
        for (int r = 0; r < 4; r++) {
            int idx = tid + r * 256;
            int kk = idx & 15, oo = idx >> 4;
            Ws[oo][kk] = W[(size_t)(o0 + oo) * C + c0 + kk];
        }
        #pragma unroll
        for (int r = 0; r < 4; r++) {
            int idx = tid + r * 256;
            int kk = idx >> 6, nn = idx & 63;
            Xs[kk][nn] = Xb[(size_t)(c0 + kk) * NTOK + nn];
        }
        __syncthreads();
        #pragma unroll
        for (int kk = 0; kk < 16; kk++) {
            float wv[4], xv[4];
            #pragma unroll
            for (int t = 0; t < 4; t++) wv[t] = Ws[ty * 4 + t][kk];
            #pragma unroll
            for (int t = 0; t < 4; t++) xv[t] = Xs[kk][tx * 4 + t];
            #pragma unroll
            for (int a = 0; a < 4; a++)
                #pragma unroll
                for (int c = 0; c < 4; c++) acc[a][c] += wv[a] * xv[c];
        }
    }
    #pragma unroll
    for (int a = 0; a < 4; a++) {
        int o = o0 + ty * 4 + a;
        float bv = bias[o];
        float4 r4;
        r4.x = (acc[a][0] + bv) * scale;
        r4.y = (acc[a][1] + bv) * scale;
        r4.z = (acc[a][2] + bv) * scale;
        r4.w = (acc[a][3] + bv) * scale;
        *reinterpret_cast<float4*>(Y + ((size_t)b * O + o) * NTOK + n0 + tx * 4) = r4;
    }
}

// ---------------------------------------------------------------------------
// Stage 2: fused flash-attention + gamma*out + skip.
// Block: 256 threads, one (batch, 32-query tile). Thread (ii = tid&31,
// grp = tid>>5) owns acc[32] = out channels [grp*32, grp*32+32) for query ii.
// Streams 64-key tiles: scores -> smem, online softmax (redundant per grp),
// PV accumulate with broadcast float4 v reads (1 LDS.128 / 4 FMA).
// q was pre-scaled by log2(e), so softmax uses exp2.
// ---------------------------------------------------------------------------
__global__ __launch_bounds__(256, 2)
void attn_kernel(const float* __restrict__ skip, const float* __restrict__ gamma,
                 float* __restrict__ out) {
    extern __shared__ float sm[];
    float* qs = sm;                       // [TI][65]  (q^T tile, padded)
    float* ks = qs + TI * 65;             // [DQK][TJ]
    float* ss = ks + DQK * TJ;            // [TI][65]  (scores, padded)
    float* vs = ss + TI * 65;             // [CVCH][TJ]

    const int b   = blockIdx.y;
    const int i0  = blockIdx.x * TI;
    const int tid = threadIdx.x;
    const int ii  = tid & 31;
    const int grp = tid >> 5;  // 0..7

    const float* qb = g_q + (size_t)b * DQK * NTOK;
    const float* kb = g_k + (size_t)b * DQK * NTOK;
    const float* vb = g_v + (size_t)b * CVCH * NTOK;

    // Load q tile transposed: qs[i][d]
    for (int idx = tid; idx < DQK * TI; idx += 256) {
        int d = idx >> 5;
        int i = idx & 31;
        qs[i * 65 + d] = qb[(size_t)d * NTOK + i0 + i];
    }

    float acc[32];
    #pragma unroll
    for (int c = 0; c < 32; c++) acc[c] = 0.f;
    float m = -1e30f;   // running max (log2 domain)
    float l = 0.f;      // running denom

    for (int j0 = 0; j0 < NTOK; j0 += TJ) {
        __syncthreads();   // previous tile's vs/ks/ss reads complete
        // Load k tile [d][j] and v tile [c][j] as float4
        #pragma unroll 4
        for (int idx = tid; idx < DQK * (TJ / 4); idx += 256) {
            int d = idx >> 4, j4 = idx & 15;
            reinterpret_cast<float4*>(ks)[d * 16 + j4] =
                *reinterpret_cast<const float4*>(kb + (size_t)d * NTOK + j0 + j4 * 4);
        }
        #pragma unroll 4
        for (int idx = tid; idx < CVCH * (TJ / 4); idx += 256) {
            int c = idx >> 4, j4 = idx & 15;
            reinterpret_cast<float4*>(vs)[c * 16 + j4] =
                *reinterpret_cast<const float4*>(vb + (size_t)c * NTOK + j0 + j4 * 4);
        }
        __syncthreads();

        // Scores: thread computes s[ii][jb..jb+7]
        {
            float s[8];
            #pragma unroll
            for (int t = 0; t < 8; t++) s[t] = 0.f;
            const int jb = grp << 3;
            #pragma unroll
            for (int d = 0; d < DQK; d++) {
                float qd = qs[ii * 65 + d];
                const float4* kr = reinterpret_cast<const float4*>(ks + d * TJ + jb);
                float4 k0 = kr[0];
                float4 k1 = kr[1];
                s[0] += qd * k0.x; s[1] += qd * k0.y;
                s[2] += qd * k0.z; s[3] += qd * k0.w;
                s[4] += qd * k1.x; s[5] += qd * k1.y;
                s[6] += qd * k1.z; s[7] += qd * k1.w;
            }
            #pragma unroll
            for (int t = 0; t < 8; t++) ss[ii * 65 + jb + t] = s[t];
        }
        __syncthreads();

        // Online softmax (redundant across the 8 groups of each i — cheap)
        float tmax = -1e30f;
        #pragma unroll
        for (int j = 0; j < TJ; j++) tmax = fmaxf(tmax, ss[ii * 65 + j]);
        float m_new = fmaxf(m, tmax);
        float corr = fast_exp2(m - m_new);
        m = m_new;
        l *= corr;
        #pragma unroll
        for (int c = 0; c < 32; c++) acc[c] *= corr;

        // PV accumulate in two 32-j halves; p kept in registers
        #pragma unroll
        for (int half = 0; half < 2; half++) {
            float p[32];
            float ps = 0.f;
            #pragma unroll
            for (int j = 0; j < 32; j++) {
                float pv = fast_exp2(ss[ii * 65 + half * 32 + j] - m_new);
                p[j] = pv;
                ps += pv;
            }
            l += ps;
            const float* vbase = vs + ((size_t)(grp << 5)) * TJ + half * 32;
            #pragma unroll
            for (int c = 0; c < 32; c++) {
                const float4* vr = reinterpret_cast<const float4*>(vbase + (size_t)c * TJ);
                float a = acc[c];
                #pragma unroll
                for (int j4 = 0; j4 < 8; j4++) {
                    float4 vv = vr[j4];   // broadcast across the warp (same c,j; i differs)
                    a += p[j4 * 4 + 0] * vv.x;
                    a += p[j4 * 4 + 1] * vv.y;
                    a += p[j4 * 4 + 2] * vv.z;
                    a += p[j4 * 4 + 3] * vv.w;
                }
                acc[c] = a;
            }
        }
    }

    // Epilogue: out = gamma * (acc / l) + skip  (coalesced over ii per channel)
    float inv = __ldg(gamma) / l;
    const float* skb = skip + (size_t)b * CVCH * NTOK + i0 + ii;
    float* ob = out + (size_t)b * CVCH * NTOK + i0 + ii;
    #pragma unroll
    for (int c = 0; c < 32; c++) {
        size_t off = (size_t)((grp << 5) + c) * NTOK;
        ob[off] = acc[c] * inv + skb[off];
    }
}

// ---------------------------------------------------------------------------
static float* s_q = nullptr;
static float* s_k = nullptr;
static float* s_v = nullptr;

static constexpr int ATTN_SMEM = (TI * 65 + DQK * TJ + TI * 65 + CVCH * TJ) * 4; // 98560 B

extern "C" void kernel_launch(void* const* d_in, const int* in_sizes, int n_in,
                              void* d_out, int out_size) {
    (void)in_sizes; (void)n_in; (void)out_size;

    // One-time setup on the first (uncaptured) correctness call.
    static bool initialized = []() {
        void* p;
        cudaGetSymbolAddress(&p, g_q); s_q = (float*)p;
        cudaGetSymbolAddress(&p, g_k); s_k = (float*)p;
        cudaGetSymbolAddress(&p, g_v); s_v = (float*)p;
        cudaFuncSetAttribute(attn_kernel, cudaFuncAttributeMaxDynamicSharedMemorySize,
                             ATTN_SMEM);
        return true;
    }();
    (void)initialized;

    const float* gate  = (const float*)d_in[0];
    const float* skip  = (const float*)d_in[1];
    const float* Wq    = (const float*)d_in[2];
    const float* bq    = (const float*)d_in[3];
    const float* Wk    = (const float*)d_in[4];
    const float* bk    = (const float*)d_in[5];
    const float* Wv    = (const float*)d_in[6];
    const float* bv    = (const float*)d_in[7];
    const float* gamma = (const float*)d_in[8];
    float* out = (float*)d_out;

    const float LOG2E = 1.4426950408889634f;  // fold into q so softmax uses exp2

    // q = log2e * (Wq @ gate + bq)   [B,64,N]
    conv1x1_kernel<<<dim3(NTOK / 64, 1, NB), 256>>>(gate, Wq, bq, s_q, 512, LOG2E);
    // k = Wk @ skip + bk             [B,64,N]
    conv1x1_kernel<<<dim3(NTOK / 64, 1, NB), 256>>>(skip, Wk, bk, s_k, 256, 1.0f);
    // v = Wv @ skip + bv             [B,256,N]
    conv1x1_kernel<<<dim3(NTOK / 64, 4, NB), 256>>>(skip, Wv, bv, s_v, 256, 1.0f);
    // fused attention + gamma*out + skip
    attn_kernel<<<dim3(NTOK / TI, NB), 256, ATTN_SMEM>>>(skip, gamma, out);
}

// round 4
// speedup vs baseline: 2.7649x; 2.7649x over previous
#include <cuda_runtime.h>
#include <cstdint>
#include <cstddef>

// Fixed shapes
#define NTOK 4096   // H*W
#define DQK  64     // INTER
#define CVCH 256    // CS
#define NB   4
#define TQ   64     // queries per CTA
#define TK   32     // keys per tile
#define NT   (NTOK / TK)   // 128 tiles

// Scratch (no cudaMalloc allowed)
__device__ float g_q[NB * DQK * NTOK];   // [b][d][n]
__device__ float g_k[NB * DQK * NTOK];   // [b][d][n]
__device__ float g_v[NB * CVCH * NTOK];  // [b][c][n]

__device__ __forceinline__ float fast_exp2(float x) {
    float r; asm("ex2.approx.ftz.f32 %0, %1;" : "=f"(r) : "f"(x)); return r;
}
__device__ __forceinline__ float tf32_rna(float x) {
    uint32_t u; asm("cvt.rna.tf32.f32 %0, %1;" : "=r"(u) : "f"(x));
    return __uint_as_float(u);
}

// m16n8k8 tf32 mma: D += A*B. A 16x8 (4 regs), B 8x8 (2 regs), D 16x8 f32 (4).
#define MMA8(d, a0, a1, a2, a3, b0, b1) \
    asm volatile("mma.sync.aligned.m16n8k8.row.col.f32.tf32.tf32.f32 " \
        "{%0,%1,%2,%3}, {%4,%5,%6,%7}, {%8,%9}, {%0,%1,%2,%3};" \
        : "+f"((d)[0]), "+f"((d)[1]), "+f"((d)[2]), "+f"((d)[3]) \
        : "r"(__float_as_uint(a0)), "r"(__float_as_uint(a1)), \
          "r"(__float_as_uint(a2)), "r"(__float_as_uint(a3)), \
          "r"(__float_as_uint(b0)), "r"(__float_as_uint(b1)))

// SMEM float offsets (strides chosen for conflict-free fragment access)
#define QHI  0        // [64 d][72]   q hi (tf32)
#define QLO  4608     // [64 d][72]   q lo
#define KHI  9216     // [64 d][40]   k hi
#define KLO  11776    // [64 d][40]   k lo
#define VS   14336    // [256 c][40]  v (tf32)
#define PS   24576    // [64 i][40]   p (tf32)
#define LRED 27136    // [64][2]
#define SMF  27264
#define ATTN_SMEM (SMF * 4)   // 109,056 B -> 2 CTAs/SM

// ---------------------------------------------------------------------------
// Stage 1: 1x1 conv == GEMM (validated in R1)
// ---------------------------------------------------------------------------
__global__ __launch_bounds__(256)
void conv1x1_kernel(const float* __restrict__ X, const float* __restrict__ W,
                    const float* __restrict__ bias, float* __restrict__ Y,
                    int C, float scale) {
    __shared__ float Ws[64][17];
    __shared__ float Xs[16][64];
    const int b  = blockIdx.z;
    const int O  = gridDim.y << 6;
    const int o0 = blockIdx.y << 6;
    const int n0 = blockIdx.x << 6;
    const int tid = threadIdx.x;
    const int tx = tid & 15;
    const int ty = tid >> 4;
    float acc[4][4];
    #pragma unroll
    for (int a = 0; a < 4; a++)
        #pragma unroll
        for (int c = 0; c < 4; c++) acc[a][c] = 0.f;

    const float* Xb = X + ((size_t)b * C) * NTOK + n0;
    for (int c0 = 0; c0 < C; c0 += 16) {
        __syncthreads();
        #pragma unroll
        for (int r = 0; r < 4; r++) {
            int idx = tid + r * 256;
            int kk = idx & 15, oo = idx >> 4;
            Ws[oo][kk] = W[(size_t)(o0 + oo) * C + c0 + kk];
        }
        #pragma unroll
        for (int r = 0; r < 4; r++) {
            int idx = tid + r * 256;
            int kk = idx >> 6, nn = idx & 63;
            Xs[kk][nn] = Xb[(size_t)(c0 + kk) * NTOK + nn];
        }
        __syncthreads();
        #pragma unroll
        for (int kk = 0; kk < 16; kk++) {
            float wv[4], xv[4];
            #pragma unroll
            for (int t = 0; t < 4; t++) wv[t] = Ws[ty * 4 + t][kk];
            #pragma unroll
            for (int t = 0; t < 4; t++) xv[t] = Xs[kk][tx * 4 + t];
            #pragma unroll
            for (int a = 0; a < 4; a++)
                #pragma unroll
                for (int c = 0; c < 4; c++) acc[a][c] += wv[a] * xv[c];
        }
    }
    #pragma unroll
    for (int a = 0; a < 4; a++) {
        int o = o0 + ty * 4 + a;
        float bv = bias[o];
        float4 r4;
        r4.x = (acc[a][0] + bv) * scale;
        r4.y = (acc[a][1] + bv) * scale;
        r4.z = (acc[a][2] + bv) * scale;
        r4.w = (acc[a][3] + bv) * scale;
        *reinterpret_cast<float4*>(Y + ((size_t)b * O + o) * NTOK + n0 + tx * 4) = r4;
    }
}

// ---------------------------------------------------------------------------
// Stage 2: flash attention on legacy tensor cores (mma.sync tf32).
// CTA = 64 queries of one batch, 8 warps, 128 key tiles of 32.
// S = Q.K^T: 3-pass tf32 hi/lo (fp32-accurate). P = exp2(S) unnormalized
// (fits fp32, no online max). O += P.V^T in registers across all tiles.
// Epilogue: out = gamma*O/l + skip.
// ---------------------------------------------------------------------------
__global__ __launch_bounds__(256, 2)
void attn_mma_kernel(const float* __restrict__ skip, const float* __restrict__ gamma,
                     float* __restrict__ out) {
    extern __shared__ float smf[];
    const int tid  = threadIdx.x;
    const int lane = tid & 31;
    const int w    = tid >> 5;
    const int gid  = lane >> 2;   // 0..7
    const int tig  = lane & 3;    // 0..3
    // S partition: rows 16*(w&3), cols 16*(w>>2)
    const int r0 = (w & 3) << 4;
    const int c0 = (w >> 2) << 4;
    // PV partition: rows 32*(w&1), cols 64*(w>>1)
    const int rq = (w & 1) << 5;
    const int cq = (w >> 1) << 6;

    const int b  = blockIdx.y;
    const int i0 = blockIdx.x * TQ;

    const float* qb = g_q + (size_t)b * DQK * NTOK;
    const float* kb = g_k + (size_t)b * DQK * NTOK;
    const float* vb = g_v + (size_t)b * CVCH * NTOK;

    // ---- Stage Q (once): [64 d][64 i] hi/lo, stride 72 ----
    {
        const int qd = tid >> 4;          // 0..15
        const int qi = (tid & 15) << 2;   // 0..60
        #pragma unroll
        for (int p = 0; p < 4; p++) {
            int d = p * 16 + qd;
            float4 x = *reinterpret_cast<const float4*>(qb + (size_t)d * NTOK + i0 + qi);
            float4 h, l4;
            h.x = tf32_rna(x.x); h.y = tf32_rna(x.y);
            h.z = tf32_rna(x.z); h.w = tf32_rna(x.w);
            l4.x = x.x - h.x; l4.y = x.y - h.y;
            l4.z = x.z - h.z; l4.w = x.w - h.w;
            *reinterpret_cast<float4*>(smf + QHI + d * 72 + qi) = h;
            *reinterpret_cast<float4*>(smf + QLO + d * 72 + qi) = l4;
        }
    }

    float oacc[16][4];
    #pragma unroll
    for (int t = 0; t < 16; t++)
        #pragma unroll
        for (int e = 0; e < 4; e++) oacc[t][e] = 0.f;
    float lsum0 = 0.f, lsum1 = 0.f;

    const int sd = tid >> 3;          // 0..31
    const int sj = (tid & 7) << 2;    // 0..28

    for (int t = 0; t < NT; t++) {
        const int j0 = t * TK;
        if (t > 0) __syncthreads();   // prior tile fully consumed

        // ---- Stage K [64 d][32 j] hi/lo (stride 40) ----
        #pragma unroll
        for (int p = 0; p < 2; p++) {
            int d = p * 32 + sd;
            float4 x = *reinterpret_cast<const float4*>(kb + (size_t)d * NTOK + j0 + sj);
            float4 h, l4;
            h.x = tf32_rna(x.x); h.y = tf32_rna(x.y);
            h.z = tf32_rna(x.z); h.w = tf32_rna(x.w);
            l4.x = x.x - h.x; l4.y = x.y - h.y;
            l4.z = x.z - h.z; l4.w = x.w - h.w;
            *reinterpret_cast<float4*>(smf + KHI + d * 40 + sj) = h;
            *reinterpret_cast<float4*>(smf + KLO + d * 40 + sj) = l4;
        }
        // ---- Stage V [256 c][32 j] tf32 (stride 40) ----
        #pragma unroll
        for (int p = 0; p < 8; p++) {
            int c = p * 32 + sd;
            float4 x = *reinterpret_cast<const float4*>(vb + (size_t)c * NTOK + j0 + sj);
            x.x = tf32_rna(x.x); x.y = tf32_rna(x.y);
            x.z = tf32_rna(x.z); x.w = tf32_rna(x.w);
            *reinterpret_cast<float4*>(smf + VS + c * 40 + sj) = x;
        }
        __syncthreads();

        // ---- S = Q.K^T (3-pass tf32), warp tile 16x16 ----
        float sacc[2][4];
        #pragma unroll
        for (int tt = 0; tt < 2; tt++)
            #pragma unroll
            for (int e = 0; e < 4; e++) sacc[tt][e] = 0.f;

        #pragma unroll
        for (int kk = 0; kk < 8; kk++) {
            const int d0 = kk * 8;
            float ah0 = smf[QHI + (d0 + tig) * 72 + r0 + gid];
            float ah1 = smf[QHI + (d0 + tig) * 72 + r0 + gid + 8];
            float ah2 = smf[QHI + (d0 + tig + 4) * 72 + r0 + gid];
            float ah3 = smf[QHI + (d0 + tig + 4) * 72 + r0 + gid + 8];
            float al0 = smf[QLO + (d0 + tig) * 72 + r0 + gid];
            float al1 = smf[QLO + (d0 + tig) * 72 + r0 + gid + 8];
            float al2 = smf[QLO + (d0 + tig + 4) * 72 + r0 + gid];
            float al3 = smf[QLO + (d0 + tig + 4) * 72 + r0 + gid + 8];
            #pragma unroll
            for (int tt = 0; tt < 2; tt++) {
                const int jc = c0 + tt * 8;
                float bh0 = smf[KHI + (d0 + tig) * 40 + jc + gid];
                float bh1 = smf[KHI + (d0 + tig + 4) * 40 + jc + gid];
                float bl0 = smf[KLO + (d0 + tig) * 40 + jc + gid];
                float bl1 = smf[KLO + (d0 + tig + 4) * 40 + jc + gid];
                MMA8(sacc[tt], ah0, ah1, ah2, ah3, bh0, bh1);
                MMA8(sacc[tt], ah0, ah1, ah2, ah3, bl0, bl1);
                MMA8(sacc[tt], al0, al1, al2, al3, bh0, bh1);
            }
        }

        // ---- softmax numerators -> P (tf32) ----
        #pragma unroll
        for (int tt = 0; tt < 2; tt++) {
            float p0 = tf32_rna(fast_exp2(sacc[tt][0]));
            float p1 = tf32_rna(fast_exp2(sacc[tt][1]));
            float p2 = tf32_rna(fast_exp2(sacc[tt][2]));
            float p3 = tf32_rna(fast_exp2(sacc[tt][3]));
            lsum0 += p0 + p1;
            lsum1 += p2 + p3;
            const int jj = c0 + tt * 8 + 2 * tig;
            *reinterpret_cast<float2*>(smf + PS + (r0 + gid) * 40 + jj)     = make_float2(p0, p1);
            *reinterpret_cast<float2*>(smf + PS + (r0 + gid + 8) * 40 + jj) = make_float2(p2, p3);
        }
        __syncthreads();

        // ---- O += P.V^T, warp tile 32x64 (2 m-tiles x 8 n-tiles) ----
        #pragma unroll
        for (int kk = 0; kk < 4; kk++) {
            const int jb = kk * 8;
            float a0[2], a1[2], a2[2], a3[2];
            #pragma unroll
            for (int mt = 0; mt < 2; mt++) {
                const int rr = rq + mt * 16;
                a0[mt] = smf[PS + (rr + gid) * 40 + jb + tig];
                a1[mt] = smf[PS + (rr + gid + 8) * 40 + jb + tig];
                a2[mt] = smf[PS + (rr + gid) * 40 + jb + tig + 4];
                a3[mt] = smf[PS + (rr + gid + 8) * 40 + jb + tig + 4];
            }
            #pragma unroll
            for (int nt = 0; nt < 8; nt++) {
                const int cc = cq + nt * 8;
                float b0 = smf[VS + (cc + gid) * 40 + jb + tig];
                float b1 = smf[VS + (cc + gid) * 40 + jb + tig + 4];
                MMA8(oacc[nt],     a0[0], a1[0], a2[0], a3[0], b0, b1);
                MMA8(oacc[8 + nt], a0[1], a1[1], a2[1], a3[1], b0, b1);
            }
        }
    }

    // ---- l reduction: quad shfl + cross warp-pair via smem ----
    lsum0 += __shfl_xor_sync(0xFFFFFFFFu, lsum0, 1);
    lsum0 += __shfl_xor_sync(0xFFFFFFFFu, lsum0, 2);
    lsum1 += __shfl_xor_sync(0xFFFFFFFFu, lsum1, 1);
    lsum1 += __shfl_xor_sync(0xFFFFFFFFu, lsum1, 2);
    __syncthreads();   // all PV reads of PS complete before LRED reuse region
    if (tig == 0) {
        smf[LRED + (r0 + gid) * 2 + (w >> 2)]     = lsum0;
        smf[LRED + (r0 + gid + 8) * 2 + (w >> 2)] = lsum1;
    }
    __syncthreads();

    const float gm = __ldg(gamma);
    const float* skb = skip + (size_t)b * CVCH * NTOK;
    float* ob = out + (size_t)b * CVCH * NTOK;

    #pragma unroll
    for (int mt = 0; mt < 2; mt++) {
        const int rlo = rq + mt * 16 + gid;
        const int rhi = rlo + 8;
        const float f0 = gm / (smf[LRED + rlo * 2] + smf[LRED + rlo * 2 + 1]);
        const float f1 = gm / (smf[LRED + rhi * 2] + smf[LRED + rhi * 2 + 1]);
        const int ilo = i0 + rlo, ihi = i0 + rhi;
        #pragma unroll
        for (int nt = 0; nt < 8; nt++) {
            const int c = cq + nt * 8 + 2 * tig;
            const size_t o0 = (size_t)c * NTOK;
            const size_t o1 = (size_t)(c + 1) * NTOK;
            const float* acc = oacc[mt * 8 + nt];
            ob[o0 + ilo] = acc[0] * f0 + skb[o0 + ilo];
            ob[o1 + ilo] = acc[1] * f0 + skb[o1 + ilo];
            ob[o0 + ihi] = acc[2] * f1 + skb[o0 + ihi];
            ob[o1 + ihi] = acc[3] * f1 + skb[o1 + ihi];
        }
    }
}

// ---------------------------------------------------------------------------
static float* s_q = nullptr;
static float* s_k = nullptr;
static float* s_v = nullptr;

extern "C" void kernel_launch(void* const* d_in, const int* in_sizes, int n_in,
                              void* d_out, int out_size) {
    (void)in_sizes; (void)n_in; (void)out_size;

    static bool initialized = []() {
        void* p;
        cudaGetSymbolAddress(&p, g_q); s_q = (float*)p;
        cudaGetSymbolAddress(&p, g_k); s_k = (float*)p;
        cudaGetSymbolAddress(&p, g_v); s_v = (float*)p;
        cudaFuncSetAttribute(attn_mma_kernel, cudaFuncAttributeMaxDynamicSharedMemorySize,
                             ATTN_SMEM);
        return true;
    }();
    (void)initialized;

    const float* gate  = (const float*)d_in[0];
    const float* skip  = (const float*)d_in[1];
    const float* Wq    = (const float*)d_in[2];
    const float* bq    = (const float*)d_in[3];
    const float* Wk    = (const float*)d_in[4];
    const float* bk    = (const float*)d_in[5];
    const float* Wv    = (const float*)d_in[6];
    const float* bv    = (const float*)d_in[7];
    const float* gamma = (const float*)d_in[8];
    float* out = (float*)d_out;

    const float LOG2E = 1.4426950408889634f;  // fold into q: softmax via exp2

    conv1x1_kernel<<<dim3(NTOK / 64, 1, NB), 256>>>(gate, Wq, bq, s_q, 512, LOG2E);
    conv1x1_kernel<<<dim3(NTOK / 64, 1, NB), 256>>>(skip, Wk, bk, s_k, 256, 1.0f);
    conv1x1_kernel<<<dim3(NTOK / 64, 4, NB), 256>>>(skip, Wv, bv, s_v, 256, 1.0f);
    attn_mma_kernel<<<dim3(NTOK / TQ, NB), 256, ATTN_SMEM>>>(skip, gamma, out);
}

// round 6
// speedup vs baseline: 3.1843x; 1.1517x over previous
#include <cuda_runtime.h>
#include <cuda_fp16.h>
#include <cstdint>
#include <cstddef>

#define NTOK 4096
#define DQK  64
#define CVCH 256
#define NB   4
#define TQ   128
#define TK   32
#define NT   (NTOK / TK)

// Scratch (no cudaMalloc). q,k TRANSPOSED [b][n][d]; v fp16 [b][c][n].
__device__ float  g_q[NB * NTOK * DQK];
__device__ float  g_k[NB * NTOK * DQK];
__device__ __half g_v[NB * CVCH * NTOK];

__device__ __forceinline__ float fast_exp2(float x) {
    float r; asm("ex2.approx.ftz.f32 %0, %1;" : "=f"(r) : "f"(x)); return r;
}

// m16n8k16 fp16 mma, fp32 accum. A 4x b32 (8 halves), B 2x b32, D 4x f32.
#define MMA16(d, a0, a1, a2, a3, b0, b1) \
    asm volatile("mma.sync.aligned.m16n8k16.row.col.f32.f16.f16.f32 " \
        "{%0,%1,%2,%3}, {%4,%5,%6,%7}, {%8,%9}, {%0,%1,%2,%3};" \
        : "+f"((d)[0]), "+f"((d)[1]), "+f"((d)[2]), "+f"((d)[3]) \
        : "r"(a0), "r"(a1), "r"(a2), "r"(a3), "r"(b0), "r"(b1))

// smem half-index offsets (strides 72/40 halves -> conflict-free frags)
#define QH 0        // [128 i][72 d] hi
#define QL 9216     // lo
#define KH 18432    // [32 j][72 d] hi
#define KL 20736    // lo
#define PH 23040    // [128 i][40 j]
#define FOFF_BYTES 56320         // float region after 28160 halves
#define RM 0        // rowmax [128][2]
#define FF 256      // rescale factor [128]
#define LR 384      // l partials [128][2]
#define ATTN_SMEM (FOFF_BYTES + 640 * 4)   // 58,880 B

__device__ __forceinline__ void split8(const float4 x, uint2& hi, uint2& lo) {
    __half h0 = __float2half_rn(x.x), h1 = __float2half_rn(x.y);
    __half h2 = __float2half_rn(x.z), h3 = __float2half_rn(x.w);
    __half e0 = __float2half_rn(x.x - __half2float(h0));
    __half e1 = __float2half_rn(x.y - __half2float(h1));
    __half e2 = __float2half_rn(x.z - __half2float(h2));
    __half e3 = __float2half_rn(x.w - __half2float(h3));
    __half2 a = __halves2half2(h0, h1), b = __halves2half2(h2, h3);
    __half2 c = __halves2half2(e0, e1), d = __halves2half2(e2, e3);
    hi.x = *(uint32_t*)&a; hi.y = *(uint32_t*)&b;
    lo.x = *(uint32_t*)&c; lo.y = *(uint32_t*)&d;
}

// ---------------------------------------------------------------------------
// 1x1 convs. A) transposed float output [b][n][64] (for q,k).
// ---------------------------------------------------------------------------
__global__ __launch_bounds__(256)
void conv_qk_T(const float* __restrict__ X, const float* __restrict__ W,
               const float* __restrict__ bias, float* __restrict__ Y,
               int C, float scale) {
    __shared__ float Ws[64][17];
    __shared__ float Xs[16][64];
    const int b = blockIdx.z, n0 = blockIdx.x << 6;
    const int tid = threadIdx.x, tx = tid & 15, ty = tid >> 4;
    float acc[4][4];
    #pragma unroll
    for (int a = 0; a < 4; a++)
        #pragma unroll
        for (int c = 0; c < 4; c++) acc[a][c] = 0.f;
    const float* Xb = X + ((size_t)b * C) * NTOK + n0;
    for (int c0 = 0; c0 < C; c0 += 16) {
        __syncthreads();
        #pragma unroll
        for (int r = 0; r < 4; r++) {
            int idx = tid + r * 256;
            Ws[idx >> 4][idx & 15] = W[(size_t)(idx >> 4) * C + c0 + (idx & 15)];
        }
        #pragma unroll
        for (int r = 0; r < 4; r++) {
            int idx = tid + r * 256;
            Xs[idx >> 6][idx & 63] = Xb[(size_t)(c0 + (idx >> 6)) * NTOK + (idx & 63)];
        }
        __syncthreads();
        #pragma unroll
        for (int kk = 0; kk < 16; kk++) {
            float wv[4], xv[4];
            #pragma unroll
            for (int t = 0; t < 4; t++) wv[t] = Ws[ty * 4 + t][kk];
            #pragma unroll
            for (int t = 0; t < 4; t++) xv[t] = Xs[kk][tx * 4 + t];
            #pragma unroll
            for (int a = 0; a < 4; a++)
                #pragma unroll
                for (int c = 0; c < 4; c++) acc[a][c] += wv[a] * xv[c];
        }
    }
    float bv[4];
    #pragma unroll
    for (int a = 0; a < 4; a++) bv[a] = bias[ty * 4 + a];
    #pragma unroll
    for (int c = 0; c < 4; c++) {
        float4 r4;
        r4.x = (acc[0][c] + bv[0]) * scale;
        r4.y = (acc[1][c] + bv[1]) * scale;
        r4.z = (acc[2][c] + bv[2]) * scale;
        r4.w = (acc[3][c] + bv[3]) * scale;
        *reinterpret_cast<float4*>(Y + ((size_t)b * NTOK + n0 + tx * 4 + c) * 64 + ty * 4) = r4;
    }
}

// B) half output [b][o][n] (for v).
__global__ __launch_bounds__(256)
void conv_v_h(const float* __restrict__ X, const float* __restrict__ W,
              const float* __restrict__ bias, __half* __restrict__ Y, int C) {
    __shared__ float Ws[64][17];
    __shared__ float Xs[16][64];
    const int b = blockIdx.z, o0 = blockIdx.y << 6, n0 = blockIdx.x << 6;
    const int tid = threadIdx.x, tx = tid & 15, ty = tid >> 4;
    float acc[4][4];
    #pragma unroll
    for (int a = 0; a < 4; a++)
        #pragma unroll
        for (int c = 0; c < 4; c++) acc[a][c] = 0.f;
    const float* Xb = X + ((size_t)b * C) * NTOK + n0;
    for (int c0 = 0; c0 < C; c0 += 16) {
        __syncthreads();
        #pragma unroll
        for (int r = 0; r < 4; r++) {
            int idx = tid + r * 256;
            Ws[idx >> 4][idx & 15] = W[(size_t)(o0 + (idx >> 4)) * C + c0 + (idx & 15)];
        }
        #pragma unroll
        for (int r = 0; r < 4; r++) {
            int idx = tid + r * 256;
            Xs[idx >> 6][idx & 63] = Xb[(size_t)(c0 + (idx >> 6)) * NTOK + (idx & 63)];
        }
        __syncthreads();
        #pragma unroll
        for (int kk = 0; kk < 16; kk++) {
            float wv[4], xv[4];
            #pragma unroll
            for (int t = 0; t < 4; t++) wv[t] = Ws[ty * 4 + t][kk];
            #pragma unroll
            for (int t = 0; t < 4; t++) xv[t] = Xs[kk][tx * 4 + t];
            #pragma unroll
            for (int a = 0; a < 4; a++)
                #pragma unroll
                for (int c = 0; c < 4; c++) acc[a][c] += wv[a] * xv[c];
        }
    }
    #pragma unroll
    for (int a = 0; a < 4; a++) {
        int o = o0 + ty * 4 + a;
        float bvv = bias[o];
        __half2 h01 = __floats2half2_rn(acc[a][0] + bvv, acc[a][1] + bvv);
        __half2 h23 = __floats2half2_rn(acc[a][2] + bvv, acc[a][3] + bvv);
        uint2 u; u.x = *(uint32_t*)&h01; u.y = *(uint32_t*)&h23;
        *reinterpret_cast<uint2*>(Y + ((size_t)b * CVCH + o) * NTOK + n0 + tx * 4) = u;
    }
}

// ---------------------------------------------------------------------------
// Flash attention, fp16 mma.sync, online softmax. 512 thr, 128 q/CTA.
// ---------------------------------------------------------------------------
__global__ __launch_bounds__(512, 1)
void attn_kernel(const float* __restrict__ skip, const float* __restrict__ gamma,
                 float* __restrict__ out) {
    extern __shared__ __align__(16) char sm[];
    __half* smh = (__half*)sm;
    float* smf = (float*)(sm + FOFF_BYTES);
    const int tid = threadIdx.x, lane = tid & 31, w = tid >> 5;
    const int gid = lane >> 2, tig = lane & 3;
    const int r0 = (w & 7) << 4;          // S rows
    const int ch = w >> 3, c0 = ch << 4;  // S col half
    const int rq = (w & 3) << 5;          // PV rows
    const int cq = (w >> 2) << 6;         // PV cols
    const int b = blockIdx.y, i0 = blockIdx.x * TQ;

    const float*  qb = g_q + (size_t)b * NTOK * DQK;
    const float*  kb = g_k + (size_t)b * NTOK * DQK;
    const __half* vb = g_v + (size_t)b * CVCH * NTOK;

    // stage Q hi/lo: [i][72 d]
    {
        const int qi = tid >> 2, d0 = (tid & 3) << 4;
        #pragma unroll
        for (int u = 0; u < 4; u++) {
            float4 x = *reinterpret_cast<const float4*>(qb + (size_t)(i0 + qi) * 64 + d0 + u * 4);
            uint2 hi, lo; split8(x, hi, lo);
            *reinterpret_cast<uint2*>(smh + QH + qi * 72 + d0 + u * 4) = hi;
            *reinterpret_cast<uint2*>(smh + QL + qi * 72 + d0 + u * 4) = lo;
        }
    }

    const int kj = tid >> 4, kd = (tid & 15) << 2;
    float4 kpre = *reinterpret_cast<const float4*>(kb + (size_t)kj * 64 + kd);

    float oacc[16][4];
    #pragma unroll
    for (int t = 0; t < 16; t++)
        #pragma unroll
        for (int e = 0; e < 4; e++) oacc[t][e] = 0.f;
    float rm0 = -1e30f, rm1 = -1e30f, lsum0 = 0.f, lsum1 = 0.f;
    const int row0 = r0 + gid, row1 = r0 + gid + 8;

    for (int t = 0; t < NT; t++) {
        const int j0 = t * TK;
        // phase 1: store prefetched K
        {
            uint2 hi, lo; split8(kpre, hi, lo);
            *reinterpret_cast<uint2*>(smh + KH + kj * 72 + kd) = hi;
            *reinterpret_cast<uint2*>(smh + KL + kj * 72 + kd) = lo;
        }
        __syncthreads();
        if (t + 1 < NT)
            kpre = *reinterpret_cast<const float4*>(kb + (size_t)(j0 + TK + kj) * 64 + kd);

        // phase 2: S = Q.K^T, fp16 3-pass, warp tile 16x16
        float sacc[2][4];
        #pragma unroll
        for (int tt = 0; tt < 2; tt++)
            #pragma unroll
            for (int e = 0; e < 4; e++) sacc[tt][e] = 0.f;
        #pragma unroll
        for (int kk = 0; kk < 4; kk++) {
            const int ab = row0 * 72 + kk * 16 + 2 * tig;
            uint32_t ah0 = *(uint32_t*)(smh + QH + ab);
            uint32_t ah1 = *(uint32_t*)(smh + QH + ab + 8 * 72);
            uint32_t ah2 = *(uint32_t*)(smh + QH + ab + 8);
            uint32_t ah3 = *(uint32_t*)(smh + QH + ab + 8 * 72 + 8);
            uint32_t al0 = *(uint32_t*)(smh + QL + ab);
            uint32_t al1 = *(uint32_t*)(smh + QL + ab + 8 * 72);
            uint32_t al2 = *(uint32_t*)(smh + QL + ab + 8);
            uint32_t al3 = *(uint32_t*)(smh + QL + ab + 8 * 72 + 8);
            #pragma unroll
            for (int tt = 0; tt < 2; tt++) {
                const int bb = (c0 + tt * 8 + gid) * 72 + kk * 16 + 2 * tig;
                uint32_t bh0 = *(uint32_t*)(smh + KH + bb);
                uint32_t bh1 = *(uint32_t*)(smh + KH + bb + 8);
                uint32_t bl0 = *(uint32_t*)(smh + KL + bb);
                uint32_t bl1 = *(uint32_t*)(smh + KL + bb + 8);
                MMA16(sacc[tt], ah0, ah1, ah2, ah3, bh0, bh1);
                MMA16(sacc[tt], ah0, ah1, ah2, ah3, bl0, bl1);
                MMA16(sacc[tt], al0, al1, al2, al3, bh0, bh1);
            }
        }
        // warp row-max (16 cols), write to smem
        float mx0 = fmaxf(fmaxf(sacc[0][0], sacc[0][1]), fmaxf(sacc[1][0], sacc[1][1]));
        float mx1 = fmaxf(fmaxf(sacc[0][2], sacc[0][3]), fmaxf(sacc[1][2], sacc[1][3]));
        mx0 = fmaxf(mx0, __shfl_xor_sync(0xFFFFFFFFu, mx0, 1));
        mx0 = fmaxf(mx0, __shfl_xor_sync(0xFFFFFFFFu, mx0, 2));
        mx1 = fmaxf(mx1, __shfl_xor_sync(0xFFFFFFFFu, mx1, 1));
        mx1 = fmaxf(mx1, __shfl_xor_sync(0xFFFFFFFFu, mx1, 2));
        if (tig == 0) {
            smf[RM + row0 * 2 + ch] = mx0;
            smf[RM + row1 * 2 + ch] = mx1;
        }
        __syncthreads();

        // phase 3: online softmax, P (fp16) to smem
        float mn0 = fmaxf(rm0, fmaxf(smf[RM + row0 * 2], smf[RM + row0 * 2 + 1]));
        float mn1 = fmaxf(rm1, fmaxf(smf[RM + row1 * 2], smf[RM + row1 * 2 + 1]));
        float f0 = fast_exp2(rm0 - mn0), f1 = fast_exp2(rm1 - mn1);
        rm0 = mn0; rm1 = mn1;
        if (tig == 0 && ch == 0) { smf[FF + row0] = f0; smf[FF + row1] = f1; }
        float ps0 = 0.f, ps1 = 0.f;
        #pragma unroll
        for (int tt = 0; tt < 2; tt++) {
            float p00 = fast_exp2(sacc[tt][0] - mn0);
            float p01 = fast_exp2(sacc[tt][1] - mn0);
            float p10 = fast_exp2(sacc[tt][2] - mn1);
            float p11 = fast_exp2(sacc[tt][3] - mn1);
            ps0 += p00 + p01; ps1 += p10 + p11;
            __half2 h0 = __floats2half2_rn(p00, p01);
            __half2 h1 = __floats2half2_rn(p10, p11);
            const int cc = c0 + tt * 8 + 2 * tig;
            *(uint32_t*)(smh + PH + row0 * 40 + cc) = *(uint32_t*)&h0;
            *(uint32_t*)(smh + PH + row1 * 40 + cc) = *(uint32_t*)&h1;
        }
        lsum0 = lsum0 * f0 + ps0;
        lsum1 = lsum1 * f1 + ps1;
        __syncthreads();

        // phase 4: rescale O, O += P.V^T (V direct from gmem fp16)
        float fa0 = smf[FF + rq + gid],      fa1 = smf[FF + rq + gid + 8];
        float fb0 = smf[FF + rq + 16 + gid], fb1 = smf[FF + rq + 16 + gid + 8];
        #pragma unroll
        for (int nt = 0; nt < 8; nt++) {
            oacc[nt][0] *= fa0; oacc[nt][1] *= fa0;
            oacc[nt][2] *= fa1; oacc[nt][3] *= fa1;
            oacc[8 + nt][0] *= fb0; oacc[8 + nt][1] *= fb0;
            oacc[8 + nt][2] *= fb1; oacc[8 + nt][3] *= fb1;
        }
        #pragma unroll
        for (int kk = 0; kk < 2; kk++) {
            const int pb = (rq + gid) * 40 + kk * 16 + 2 * tig;
            uint32_t pa0 = *(uint32_t*)(smh + PH + pb);
            uint32_t pa1 = *(uint32_t*)(smh + PH + pb + 8 * 40);
            uint32_t pa2 = *(uint32_t*)(smh + PH + pb + 8);
            uint32_t pa3 = *(uint32_t*)(smh + PH + pb + 8 * 40 + 8);
            uint32_t qa0 = *(uint32_t*)(smh + PH + pb + 16 * 40);
            uint32_t qa1 = *(uint32_t*)(smh + PH + pb + 24 * 40);
            uint32_t qa2 = *(uint32_t*)(smh + PH + pb + 16 * 40 + 8);
            uint32_t qa3 = *(uint32_t*)(smh + PH + pb + 24 * 40 + 8);
            #pragma unroll
            for (int nt = 0; nt < 8; nt++) {
                const __half* vp = vb + (size_t)(cq + nt * 8 + gid) * NTOK + j0 + kk * 16 + 2 * tig;
                uint32_t vb0 = *(const uint32_t*)vp;
                uint32_t vb1 = *(const uint32_t*)(vp + 8);
                MMA16(oacc[nt],     pa0, pa1, pa2, pa3, vb0, vb1);
                MMA16(oacc[8 + nt], qa0, qa1, qa2, qa3, vb0, vb1);
            }
        }
    }

    // final l reduction
    lsum0 += __shfl_xor_sync(0xFFFFFFFFu, lsum0, 1);
    lsum0 += __shfl_xor_sync(0xFFFFFFFFu, lsum0, 2);
    lsum1 += __shfl_xor_sync(0xFFFFFFFFu, lsum1, 1);
    lsum1 += __shfl_xor_sync(0xFFFFFFFFu, lsum1, 2);
    if (tig == 0) {
        smf[LR + row0 * 2 + ch] = lsum0;
        smf[LR + row1 * 2 + ch] = lsum1;
    }
    __syncthreads();

    const float gm = __ldg(gamma);
    const float* skb = skip + (size_t)b * CVCH * NTOK;
    float* ob = out + (size_t)b * CVCH * NTOK;
    #pragma unroll
    for (int mt = 0; mt < 2; mt++) {
        const int ra = rq + mt * 16 + gid, rb = ra + 8;
        const float fca = gm / (smf[LR + ra * 2] + smf[LR + ra * 2 + 1]);
        const float fcb = gm / (smf[LR + rb * 2] + smf[LR + rb * 2 + 1]);
        const int ia = i0 + ra, ib = i0 + rb;
        #pragma unroll
        for (int nt = 0; nt < 8; nt++) {
            const int c = cq + nt * 8 + 2 * tig;
            const size_t oA = (size_t)c * NTOK, oB = (size_t)(c + 1) * NTOK;
            const float* acc = oacc[mt * 8 + nt];
            ob[oA + ia] = acc[0] * fca + skb[oA + ia];
            ob[oB + ia] = acc[1] * fca + skb[oB + ia];
            ob[oA + ib] = acc[2] * fcb + skb[oA + ib];
            ob[oB + ib] = acc[3] * fcb + skb[oB + ib];
        }
    }
}

// ---------------------------------------------------------------------------
static float*  s_q = nullptr;
static float*  s_k = nullptr;
static __half* s_v = nullptr;

extern "C" void kernel_launch(void* const* d_in, const int* in_sizes, int n_in,
                              void* d_out, int out_size) {
    (void)in_sizes; (void)n_in; (void)out_size;
    static bool initialized = []() {
        void* p;
        cudaGetSymbolAddress(&p, g_q); s_q = (float*)p;
        cudaGetSymbolAddress(&p, g_k); s_k = (float*)p;
        cudaGetSymbolAddress(&p, g_v); s_v = (__half*)p;
        cudaFuncSetAttribute(attn_kernel, cudaFuncAttributeMaxDynamicSharedMemorySize,
                             ATTN_SMEM);
        return true;
    }();
    (void)initialized;

    const float* gate  = (const float*)d_in[0];
    const float* skip  = (const float*)d_in[1];
    const float* Wq    = (const float*)d_in[2];
    const float* bq    = (const float*)d_in[3];
    const float* Wk    = (const float*)d_in[4];
    const float* bk    = (const float*)d_in[5];
    const float* Wv    = (const float*)d_in[6];
    const float* bv    = (const float*)d_in[7];
    const float* gamma = (const float*)d_in[8];
    float* out = (float*)d_out;

    const float LOG2E = 1.4426950408889634f;  // fold into q: softmax via exp2

    conv_qk_T<<<dim3(NTOK / 64, 1, NB), 256>>>(gate, Wq, bq, s_q, 512, LOG2E);
    conv_qk_T<<<dim3(NTOK / 64, 1, NB), 256>>>(skip, Wk, bk, s_k, 256, 1.0f);
    conv_v_h <<<dim3(NTOK / 64, 4, NB), 256>>>(skip, Wv, bv, s_v, 256);
    attn_kernel<<<dim3(NTOK / TQ, NB), 512, ATTN_SMEM>>>(skip, gamma, out);
}

// round 7
// speedup vs baseline: 5.0872x; 1.5976x over previous
#include <cuda_runtime.h>
#include <cuda_fp16.h>
#include <cstdint>
#include <cstddef>

#define NTOK 4096
#define DQK  64
#define CVCH 256
#define NB   4
#define TQ   128
#define TK   64
#define NT   (NTOK / TK)   // 64 tiles

// gmem scratch (16B-aligned for cp.async)
__device__ __align__(16) __half g_q16[NB * NTOK * 128];        // [b][n][hi64|lo64]
__device__ __align__(16) __half g_k16[NB * NTOK * 128];
__device__ __align__(16) __half g_v16[NB * NT * CVCH * TK];    // tiled [b][t][c][64j]

__device__ __forceinline__ float fast_exp2(float x) {
    float r; asm("ex2.approx.ftz.f32 %0, %1;" : "=f"(r) : "f"(x)); return r;
}
__device__ __forceinline__ uint32_t smem_u32(const void* p) {
    uint32_t a;
    asm("{ .reg .u64 t; cvta.to.shared.u64 t, %1; cvt.u32.u64 %0, t; }" : "=r"(a) : "l"(p));
    return a;
}
#define MMA16(d, a0, a1, a2, a3, b0, b1) \
    asm volatile("mma.sync.aligned.m16n8k16.row.col.f32.f16.f16.f32 " \
        "{%0,%1,%2,%3}, {%4,%5,%6,%7}, {%8,%9}, {%0,%1,%2,%3};" \
        : "+f"((d)[0]), "+f"((d)[1]), "+f"((d)[2]), "+f"((d)[3]) \
        : "r"(a0), "r"(a1), "r"(a2), "r"(a3), "r"(b0), "r"(b1))
#define CP16(dst, src) \
    asm volatile("cp.async.cg.shared.global [%0], [%1], 16;" :: "r"(dst), "l"(src))
#define CPCOMMIT() asm volatile("cp.async.commit_group;")
#define CPWAIT0()  asm volatile("cp.async.wait_group 0;" ::: "memory")

// smem half-index offsets; all rows stride 72 halves (conflict-free frags)
#define SQH 0        // [128][72]
#define SQL 9216
#define SKB 18432    // 2 bufs x (KH 64x72 | KL 64x72)
#define SVB 36864    // 2 bufs x [256][72]
#define SP  73728    // [128][72]
#define FOFF 165888  // byte offset of float region
#define RM 0
#define FF 256
#define LR 384
#define ATTN_SMEM (FOFF + 640 * 4)   // 168,448 B

// ---------------------------------------------------------------------------
// conv A: q/k -> fp16 hi/lo, layout [b][n][hi64|lo64]
// ---------------------------------------------------------------------------
__global__ __launch_bounds__(256)
void conv_qk16(const float* __restrict__ X, const float* __restrict__ W,
               const float* __restrict__ bias, __half* __restrict__ Y,
               int C, float scale) {
    __shared__ float Ws[64][17];
    __shared__ float Xs[16][64];
    const int b = blockIdx.z, n0 = blockIdx.x << 6;
    const int tid = threadIdx.x, tx = tid & 15, ty = tid >> 4;
    float acc[4][4];
    #pragma unroll
    for (int a = 0; a < 4; a++)
        #pragma unroll
        for (int c = 0; c < 4; c++) acc[a][c] = 0.f;
    const float* Xb = X + ((size_t)b * C) * NTOK + n0;
    for (int c0 = 0; c0 < C; c0 += 16) {
        __syncthreads();
        #pragma unroll
        for (int r = 0; r < 4; r++) {
            int idx = tid + r * 256;
            Ws[idx >> 4][idx & 15] = W[(size_t)(idx >> 4) * C + c0 + (idx & 15)];
        }
        #pragma unroll
        for (int r = 0; r < 4; r++) {
            int idx = tid + r * 256;
            Xs[idx >> 6][idx & 63] = Xb[(size_t)(c0 + (idx >> 6)) * NTOK + (idx & 63)];
        }
        __syncthreads();
        #pragma unroll
        for (int kk = 0; kk < 16; kk++) {
            float wv[4], xv[4];
            #pragma unroll
            for (int t = 0; t < 4; t++) wv[t] = Ws[ty * 4 + t][kk];
            #pragma unroll
            for (int t = 0; t < 4; t++) xv[t] = Xs[kk][tx * 4 + t];
            #pragma unroll
            for (int a = 0; a < 4; a++)
                #pragma unroll
                for (int c = 0; c < 4; c++) acc[a][c] += wv[a] * xv[c];
        }
    }
    float bv[4];
    #pragma unroll
    for (int a = 0; a < 4; a++) bv[a] = bias[ty * 4 + a];
    #pragma unroll
    for (int c = 0; c < 4; c++) {
        int n = n0 + tx * 4 + c;
        __half h[4], l[4];
        #pragma unroll
        for (int a = 0; a < 4; a++) {
            float v = (acc[a][c] + bv[a]) * scale;
            h[a] = __float2half_rn(v);
            l[a] = __float2half_rn(v - __half2float(h[a]));
        }
        __half2 h01 = __halves2half2(h[0], h[1]), h23 = __halves2half2(h[2], h[3]);
        __half2 l01 = __halves2half2(l[0], l[1]), l23 = __halves2half2(l[2], l[3]);
        uint2 uh, ul;
        uh.x = *(uint32_t*)&h01; uh.y = *(uint32_t*)&h23;
        ul.x = *(uint32_t*)&l01; ul.y = *(uint32_t*)&l23;
        __half* yp = Y + ((size_t)b * NTOK + n) * 128 + ty * 4;
        *reinterpret_cast<uint2*>(yp)      = uh;
        *reinterpret_cast<uint2*>(yp + 64) = ul;
    }
}

// conv B: v -> fp16, tiled [b][t][c][64j]
__global__ __launch_bounds__(256)
void conv_v16(const float* __restrict__ X, const float* __restrict__ W,
              const float* __restrict__ bias, __half* __restrict__ Y, int C) {
    __shared__ float Ws[64][17];
    __shared__ float Xs[16][64];
    const int b = blockIdx.z, o0 = blockIdx.y << 6, n0 = blockIdx.x << 6;
    const int tid = threadIdx.x, tx = tid & 15, ty = tid >> 4;
    float acc[4][4];
    #pragma unroll
    for (int a = 0; a < 4; a++)
        #pragma unroll
        for (int c = 0; c < 4; c++) acc[a][c] = 0.f;
    const float* Xb = X + ((size_t)b * C) * NTOK + n0;
    for (int c0 = 0; c0 < C; c0 += 16) {
        __syncthreads();
        #pragma unroll
        for (int r = 0; r < 4; r++) {
            int idx = tid + r * 256;
            Ws[idx >> 4][idx & 15] = W[(size_t)(o0 + (idx >> 4)) * C + c0 + (idx & 15)];
        }
        #pragma unroll
        for (int r = 0; r < 4; r++) {
            int idx = tid + r * 256;
            Xs[idx >> 6][idx & 63] = Xb[(size_t)(c0 + (idx >> 6)) * NTOK + (idx & 63)];
        }
        __syncthreads();
        #pragma unroll
        for (int kk = 0; kk < 16; kk++) {
            float wv[4], xv[4];
            #pragma unroll
            for (int t = 0; t < 4; t++) wv[t] = Ws[ty * 4 + t][kk];
            #pragma unroll
            for (int t = 0; t < 4; t++) xv[t] = Xs[kk][tx * 4 + t];
            #pragma unroll
            for (int a = 0; a < 4; a++)
                #pragma unroll
                for (int c = 0; c < 4; c++) acc[a][c] += wv[a] * xv[c];
        }
    }
    const int tile = n0 >> 6;   // n0 is a multiple of 64
    #pragma unroll
    for (int a = 0; a < 4; a++) {
        int o = o0 + ty * 4 + a;
        float bvv = bias[o];
        __half2 h01 = __floats2half2_rn(acc[a][0] + bvv, acc[a][1] + bvv);
        __half2 h23 = __floats2half2_rn(acc[a][2] + bvv, acc[a][3] + bvv);
        uint2 u; u.x = *(uint32_t*)&h01; u.y = *(uint32_t*)&h23;
        *reinterpret_cast<uint2*>(Y + (((size_t)b * NT + tile) * CVCH + o) * TK + tx * 4) = u;
    }
}

// ---------------------------------------------------------------------------
// Flash attention: fp16 mma.sync, cp.async double-buffered K/V, TK=64.
// ---------------------------------------------------------------------------
__global__ __launch_bounds__(512, 1)
void attn_kernel(const float* __restrict__ skip, const float* __restrict__ gamma,
                 float* __restrict__ out) {
    extern __shared__ __align__(16) char sm[];
    __half* smh = (__half*)sm;
    float* smf = (float*)(sm + FOFF);
    const uint32_t sb = smem_u32(sm);
    const int tid = threadIdx.x, lane = tid & 31, w = tid >> 5;
    const int gid = lane >> 2, tig = lane & 3;
    const int r0 = (w & 7) << 4;            // S rows
    const int ch = w >> 3;                  // S col half (0/1 -> 32 cols)
    const int rq = (w & 3) << 5, cq = (w >> 2) << 6;   // PV partition
    const int b = blockIdx.y, i0 = blockIdx.x * TQ;
    const int row0 = r0 + gid, row1 = row0 + 8;

    const __half* qb = g_q16 + (size_t)b * NTOK * 128;
    const __half* kb = g_k16 + (size_t)b * NTOK * 128;
    const __half* vb = g_v16 + (size_t)b * NT * CVCH * TK;

    // prologue: stage Q + K0/V0 via cp.async
    #pragma unroll
    for (int p = 0; p < 4; p++) {
        int chunk = tid + p * 512, row = chunk >> 4, c16 = chunk & 15;
        uint32_t d = sb + 2u * (c16 < 8 ? SQH + row * 72 + c16 * 8
                                        : SQL + row * 72 + (c16 - 8) * 8);
        CP16(d, qb + (size_t)(i0 + row) * 128 + c16 * 8);
    }
    {
        const int skh = SKB, skl = SKB + 4608, sv = SVB;
        #pragma unroll
        for (int p = 0; p < 2; p++) {
            int chunk = tid + p * 512, row = chunk >> 4, c16 = chunk & 15;
            uint32_t d = sb + 2u * (c16 < 8 ? skh + row * 72 + c16 * 8
                                            : skl + row * 72 + (c16 - 8) * 8);
            CP16(d, kb + (size_t)row * 128 + c16 * 8);
        }
        #pragma unroll
        for (int p = 0; p < 4; p++) {
            int chunk = tid + p * 512, row = chunk >> 3, c8 = chunk & 7;
            CP16(sb + 2u * (sv + row * 72 + c8 * 8), vb + (size_t)row * TK + c8 * 8);
        }
    }
    CPCOMMIT();

    float oacc[16][4];
    #pragma unroll
    for (int t = 0; t < 16; t++)
        #pragma unroll
        for (int e = 0; e < 4; e++) oacc[t][e] = 0.f;
    float rm0 = -1e30f, rm1 = -1e30f, lsum0 = 0.f, lsum1 = 0.f;

    for (int t = 0; t < NT; t++) {
        const int buf = t & 1;
        CPWAIT0();
        __syncthreads();
        // issue next tile's K/V into the other buffer
        if (t + 1 < NT) {
            const int nb2 = buf ^ 1;
            const int skh = SKB + nb2 * 9216, skl = skh + 4608, sv = SVB + nb2 * 18432;
            const size_t j0n = (size_t)(t + 1) * TK;
            #pragma unroll
            for (int p = 0; p < 2; p++) {
                int chunk = tid + p * 512, row = chunk >> 4, c16 = chunk & 15;
                uint32_t d = sb + 2u * (c16 < 8 ? skh + row * 72 + c16 * 8
                                                : skl + row * 72 + (c16 - 8) * 8);
                CP16(d, kb + (j0n + row) * 128 + c16 * 8);
            }
            const __half* vt = vb + (size_t)(t + 1) * CVCH * TK;
            #pragma unroll
            for (int p = 0; p < 4; p++) {
                int chunk = tid + p * 512, row = chunk >> 3, c8 = chunk & 7;
                CP16(sb + 2u * (sv + row * 72 + c8 * 8), vt + (size_t)row * TK + c8 * 8);
            }
        }
        CPCOMMIT();

        // S = Q.K^T (fp16 3-pass), warp tile 16 rows x 32 cols
        const int kh = SKB + buf * 9216, kl = kh + 4608;
        float sacc[4][4];
        #pragma unroll
        for (int tt = 0; tt < 4; tt++)
            #pragma unroll
            for (int e = 0; e < 4; e++) sacc[tt][e] = 0.f;
        #pragma unroll
        for (int kk = 0; kk < 4; kk++) {
            const int ab = row0 * 72 + kk * 16 + 2 * tig;
            uint32_t ah0 = *(uint32_t*)(smh + SQH + ab);
            uint32_t ah1 = *(uint32_t*)(smh + SQH + ab + 8 * 72);
            uint32_t ah2 = *(uint32_t*)(smh + SQH + ab + 8);
            uint32_t ah3 = *(uint32_t*)(smh + SQH + ab + 8 * 72 + 8);
            uint32_t al0 = *(uint32_t*)(smh + SQL + ab);
            uint32_t al1 = *(uint32_t*)(smh + SQL + ab + 8 * 72);
            uint32_t al2 = *(uint32_t*)(smh + SQL + ab + 8);
            uint32_t al3 = *(uint32_t*)(smh + SQL + ab + 8 * 72 + 8);
            #pragma unroll
            for (int tt = 0; tt < 4; tt++) {
                const int bb = (ch * 32 + tt * 8 + gid) * 72 + kk * 16 + 2 * tig;
                uint32_t bh0 = *(uint32_t*)(smh + kh + bb);
                uint32_t bh1 = *(uint32_t*)(smh + kh + bb + 8);
                uint32_t bl0 = *(uint32_t*)(smh + kl + bb);
                uint32_t bl1 = *(uint32_t*)(smh + kl + bb + 8);
                MMA16(sacc[tt], ah0, ah1, ah2, ah3, bh0, bh1);
                MMA16(sacc[tt], ah0, ah1, ah2, ah3, bl0, bl1);
                MMA16(sacc[tt], al0, al1, al2, al3, bh0, bh1);
            }
        }
        float mx0 = -1e30f, mx1 = -1e30f;
        #pragma unroll
        for (int tt = 0; tt < 4; tt++) {
            mx0 = fmaxf(mx0, fmaxf(sacc[tt][0], sacc[tt][1]));
            mx1 = fmaxf(mx1, fmaxf(sacc[tt][2], sacc[tt][3]));
        }
        mx0 = fmaxf(mx0, __shfl_xor_sync(0xFFFFFFFFu, mx0, 1));
        mx0 = fmaxf(mx0, __shfl_xor_sync(0xFFFFFFFFu, mx0, 2));
        mx1 = fmaxf(mx1, __shfl_xor_sync(0xFFFFFFFFu, mx1, 1));
        mx1 = fmaxf(mx1, __shfl_xor_sync(0xFFFFFFFFu, mx1, 2));
        if (tig == 0) {
            smf[RM + row0 * 2 + ch] = mx0;
            smf[RM + row1 * 2 + ch] = mx1;
        }
        __syncthreads();

        // online softmax -> P fp16
        float mn0 = fmaxf(rm0, fmaxf(smf[RM + row0 * 2], smf[RM + row0 * 2 + 1]));
        float mn1 = fmaxf(rm1, fmaxf(smf[RM + row1 * 2], smf[RM + row1 * 2 + 1]));
        float f0 = fast_exp2(rm0 - mn0), f1 = fast_exp2(rm1 - mn1);
        rm0 = mn0; rm1 = mn1;
        if (tig == 0 && ch == 0) { smf[FF + row0] = f0; smf[FF + row1] = f1; }
        float ps0 = 0.f, ps1 = 0.f;
        #pragma unroll
        for (int tt = 0; tt < 4; tt++) {
            float p00 = fast_exp2(sacc[tt][0] - mn0);
            float p01 = fast_exp2(sacc[tt][1] - mn0);
            float p10 = fast_exp2(sacc[tt][2] - mn1);
            float p11 = fast_exp2(sacc[tt][3] - mn1);
            ps0 += p00 + p01; ps1 += p10 + p11;
            __half2 h0 = __floats2half2_rn(p00, p01);
            __half2 h1 = __floats2half2_rn(p10, p11);
            const int cc = ch * 32 + tt * 8 + 2 * tig;
            *(uint32_t*)(smh + SP + row0 * 72 + cc) = *(uint32_t*)&h0;
            *(uint32_t*)(smh + SP + row1 * 72 + cc) = *(uint32_t*)&h1;
        }
        lsum0 = lsum0 * f0 + ps0;
        lsum1 = lsum1 * f1 + ps1;
        __syncthreads();

        // rescale O, then O += P.V^T from SV buf
        const int sv = SVB + buf * 18432;
        float fa0 = smf[FF + rq + gid],      fa1 = smf[FF + rq + gid + 8];
        float fb0 = smf[FF + rq + 16 + gid], fb1 = smf[FF + rq + 16 + gid + 8];
        #pragma unroll
        for (int nt = 0; nt < 8; nt++) {
            oacc[nt][0] *= fa0; oacc[nt][1] *= fa0;
            oacc[nt][2] *= fa1; oacc[nt][3] *= fa1;
            oacc[8 + nt][0] *= fb0; oacc[8 + nt][1] *= fb0;
            oacc[8 + nt][2] *= fb1; oacc[8 + nt][3] *= fb1;
        }
        #pragma unroll
        for (int kk = 0; kk < 4; kk++) {
            const int pb = (rq + gid) * 72 + kk * 16 + 2 * tig;
            uint32_t pa0 = *(uint32_t*)(smh + SP + pb);
            uint32_t pa1 = *(uint32_t*)(smh + SP + pb + 8 * 72);
            uint32_t pa2 = *(uint32_t*)(smh + SP + pb + 8);
            uint32_t pa3 = *(uint32_t*)(smh + SP + pb + 8 * 72 + 8);
            uint32_t qa0 = *(uint32_t*)(smh + SP + pb + 16 * 72);
            uint32_t qa1 = *(uint32_t*)(smh + SP + pb + 24 * 72);
            uint32_t qa2 = *(uint32_t*)(smh + SP + pb + 16 * 72 + 8);
            uint32_t qa3 = *(uint32_t*)(smh + SP + pb + 24 * 72 + 8);
            #pragma unroll
            for (int nt = 0; nt < 8; nt++) {
                const int vB = (cq + nt * 8 + gid) * 72 + kk * 16 + 2 * tig;
                uint32_t vb0 = *(uint32_t*)(smh + sv + vB);
                uint32_t vb1 = *(uint32_t*)(smh + sv + vB + 8);
                MMA16(oacc[nt],     pa0, pa1, pa2, pa3, vb0, vb1);
                MMA16(oacc[8 + nt], qa0, qa1, qa2, qa3, vb0, vb1);
            }
        }
    }

    // final l reduction + epilogue
    lsum0 += __shfl_xor_sync(0xFFFFFFFFu, lsum0, 1);
    lsum0 += __shfl_xor_sync(0xFFFFFFFFu, lsum0, 2);
    lsum1 += __shfl_xor_sync(0xFFFFFFFFu, lsum1, 1);
    lsum1 += __shfl_xor_sync(0xFFFFFFFFu, lsum1, 2);
    if (tig == 0) {
        smf[LR + row0 * 2 + ch] = lsum0;
        smf[LR + row1 * 2 + ch] = lsum1;
    }
    __syncthreads();

    const float gm = __ldg(gamma);
    const float* skb = skip + (size_t)b * CVCH * NTOK;
    float* ob = out + (size_t)b * CVCH * NTOK;
    #pragma unroll
    for (int mt = 0; mt < 2; mt++) {
        const int ra = rq + mt * 16 + gid, rb = ra + 8;
        const float fca = gm / (smf[LR + ra * 2] + smf[LR + ra * 2 + 1]);
        const float fcb = gm / (smf[LR + rb * 2] + smf[LR + rb * 2 + 1]);
        const int ia = i0 + ra, ib = i0 + rb;
        #pragma unroll
        for (int nt = 0; nt < 8; nt++) {
            const int c = cq + nt * 8 + 2 * tig;
            const size_t oA = (size_t)c * NTOK, oB = (size_t)(c + 1) * NTOK;
            const float* acc = oacc[mt * 8 + nt];
            ob[oA + ia] = acc[0] * fca + skb[oA + ia];
            ob[oB + ia] = acc[1] * fca + skb[oB + ia];
            ob[oA + ib] = acc[2] * fcb + skb[oA + ib];
            ob[oB + ib] = acc[3] * fcb + skb[oB + ib];
        }
    }
}

// ---------------------------------------------------------------------------
static __half* s_q = nullptr;
static __half* s_k = nullptr;
static __half* s_v = nullptr;

extern "C" void kernel_launch(void* const* d_in, const int* in_sizes, int n_in,
                              void* d_out, int out_size) {
    (void)in_sizes; (void)n_in; (void)out_size;
    static bool initialized = []() {
        void* p;
        cudaGetSymbolAddress(&p, g_q16); s_q = (__half*)p;
        cudaGetSymbolAddress(&p, g_k16); s_k = (__half*)p;
        cudaGetSymbolAddress(&p, g_v16); s_v = (__half*)p;
        cudaFuncSetAttribute(attn_kernel, cudaFuncAttributeMaxDynamicSharedMemorySize,
                             ATTN_SMEM);
        return true;
    }();
    (void)initialized;

    const float* gate  = (const float*)d_in[0];
    const float* skip  = (const float*)d_in[1];
    const float* Wq    = (const float*)d_in[2];
    const float* bq    = (const float*)d_in[3];
    const float* Wk    = (const float*)d_in[4];
    const float* bk    = (const float*)d_in[5];
    const float* Wv    = (const float*)d_in[6];
    const float* bv    = (const float*)d_in[7];
    const float* gamma = (const float*)d_in[8];
    float* out = (float*)d_out;

    const float LOG2E = 1.4426950408889634f;

    conv_qk16<<<dim3(NTOK / 64, 1, NB), 256>>>(gate, Wq, bq, s_q, 512, LOG2E);
    conv_qk16<<<dim3(NTOK / 64, 1, NB), 256>>>(skip, Wk, bk, s_k, 256, 1.0f);
    conv_v16 <<<dim3(NTOK / 64, 4, NB), 256>>>(skip, Wv, bv, s_v, 256);
    attn_kernel<<<dim3(NTOK / TQ, NB), 512, ATTN_SMEM>>>(skip, gamma, out);
}

// round 8
// speedup vs baseline: 6.7134x; 1.3197x over previous
#include <cuda_runtime.h>
#include <cuda_fp16.h>
#include <cstdint>
#include <cstddef>

#define NTOK 4096
#define DQK  64
#define CVCH 256
#define NB   4
#define TQ   128
#define TK   64
#define NT   (NTOK / TK)   // 64

__device__ __align__(16) __half g_q16[NB * NTOK * 128];     // [b][n][hi64|lo64]
__device__ __align__(16) __half g_k16[NB * NTOK * 128];
__device__ __align__(16) __half g_v16[NB * NT * CVCH * TK]; // [b][t][c][64j]

__device__ __forceinline__ float fast_exp2(float x) {
    float r; asm("ex2.approx.ftz.f32 %0, %1;" : "=f"(r) : "f"(x)); return r;
}
__device__ __forceinline__ uint32_t smem_u32(const void* p) {
    uint32_t a;
    asm("{ .reg .u64 t; cvta.to.shared.u64 t, %1; cvt.u32.u64 %0, t; }" : "=r"(a) : "l"(p));
    return a;
}
#define MMA16(d, a0, a1, a2, a3, b0, b1) \
    asm volatile("mma.sync.aligned.m16n8k16.row.col.f32.f16.f16.f32 " \
        "{%0,%1,%2,%3}, {%4,%5,%6,%7}, {%8,%9}, {%0,%1,%2,%3};" \
        : "+f"((d)[0]), "+f"((d)[1]), "+f"((d)[2]), "+f"((d)[3]) \
        : "r"(a0), "r"(a1), "r"(a2), "r"(a3), "r"(b0), "r"(b1))
#define LDSM4(r0, r1, r2, r3, a) \
    asm volatile("ldmatrix.sync.aligned.m8n8.x4.shared.b16 {%0,%1,%2,%3},[%4];" \
        : "=r"(r0), "=r"(r1), "=r"(r2), "=r"(r3) : "r"(a))
#define LDSM4T(r0, r1, r2, r3, a) \
    asm volatile("ldmatrix.sync.aligned.m8n8.x4.trans.shared.b16 {%0,%1,%2,%3},[%4];" \
        : "=r"(r0), "=r"(r1), "=r"(r2), "=r"(r3) : "r"(a))
#define CP16(dst, src) \
    asm volatile("cp.async.cg.shared.global [%0], [%1], 16;" :: "r"(dst), "l"(src))
#define CPCOMMIT() asm volatile("cp.async.commit_group;")
#define CPWAIT0()  asm volatile("cp.async.wait_group 0;" ::: "memory")

__device__ __forceinline__ void split8(const float4 x, uint2& hi, uint2& lo) {
    __half h0 = __float2half_rn(x.x), h1 = __float2half_rn(x.y);
    __half h2 = __float2half_rn(x.z), h3 = __float2half_rn(x.w);
    __half e0 = __float2half_rn(x.x - __half2float(h0));
    __half e1 = __float2half_rn(x.y - __half2float(h1));
    __half e2 = __float2half_rn(x.z - __half2float(h2));
    __half e3 = __float2half_rn(x.w - __half2float(h3));
    __half2 a = __halves2half2(h0, h1), b = __halves2half2(h2, h3);
    __half2 c = __halves2half2(e0, e1), d = __halves2half2(e2, e3);
    hi.x = *(uint32_t*)&a; hi.y = *(uint32_t*)&b;
    lo.x = *(uint32_t*)&c; lo.y = *(uint32_t*)&d;
}

// attn smem layout (halves), rows stride 72
#define SQH 0
#define SQL 9216
#define SKB 18432
#define SVB 36864
#define SP  73728
#define FOFF 165888
#define RM 0
#define FF 256
#define LR 384
#define ATTN_SMEM (FOFF + 640 * 4)

// ---------------------------------------------------------------------------
// conv q/k: Y[n][hi64|lo64] = fp16-3-pass GEMM (fp32 accurate). m=tokens.
// ---------------------------------------------------------------------------
__global__ __launch_bounds__(256)
void conv_qk_mma(const float* __restrict__ X, const float* __restrict__ W,
                 const float* __restrict__ bias, __half* __restrict__ Y,
                 int C, float scale) {
    __shared__ __half smc[13824];     // XH[32][136] XL WH[64][40] WL
    __shared__ float sbias[64];
    const int XL = 4352, WH = 8704, WL = 11264;
    const int b = blockIdx.z, n0 = blockIdx.x << 7;
    const int tid = threadIdx.x, lane = tid & 31, w = tid >> 5;
    const int gid = lane >> 2, tig = lane & 3, lr = lane & 15, lc = (lane >> 4) << 3;
    const uint32_t sb = smem_u32(smc);
    if (tid < 64) sbias[tid] = bias[tid];
    float acc[8][4];
    #pragma unroll
    for (int i = 0; i < 8; i++)
        #pragma unroll
        for (int e = 0; e < 4; e++) acc[i][e] = 0.f;

    for (int c0 = 0; c0 < C; c0 += 32) {
        __syncthreads();
        #pragma unroll
        for (int p = 0; p < 4; p++) {   // X chunk [32c][128n] hi/lo
            int idx = tid + p * 256, cc = idx >> 5, n4 = (idx & 31) << 2;
            float4 x = *reinterpret_cast<const float4*>(X + ((size_t)b * C + c0 + cc) * NTOK + n0 + n4);
            uint2 hi, lo; split8(x, hi, lo);
            *reinterpret_cast<uint2*>(smc + cc * 136 + n4) = hi;
            *reinterpret_cast<uint2*>(smc + XL + cc * 136 + n4) = lo;
        }
        #pragma unroll
        for (int p = 0; p < 2; p++) {   // W chunk [64o][32c] hi/lo
            int idx = tid + p * 256, oo = idx >> 3, c4 = (idx & 7) << 2;
            float4 x = *reinterpret_cast<const float4*>(W + (size_t)oo * C + c0 + c4);
            uint2 hi, lo; split8(x, hi, lo);
            *reinterpret_cast<uint2*>(smc + WH + oo * 40 + c4) = hi;
            *reinterpret_cast<uint2*>(smc + WL + oo * 40 + c4) = lo;
        }
        __syncthreads();
        #pragma unroll
        for (int ks = 0; ks < 2; ks++) {
            uint32_t ah0, ah1, ah2, ah3, al0, al1, al2, al3;
            uint32_t ax = sb + 2u * (((ks << 4) + (lane & 7) + ((lane >> 4) << 3)) * 136
                                     + (w << 4) + (((lane >> 3) & 1) << 3));
            LDSM4T(ah0, ah1, ah2, ah3, ax);
            LDSM4T(al0, al1, al2, al3, ax + 2u * XL);
            #pragma unroll
            for (int p = 0; p < 4; p++) {
                uint32_t bh0, bh1, bh2, bh3, bl0, bl1, bl2, bl3;
                uint32_t aw = sb + 2u * (WH + ((p << 4) + lr) * 40 + (ks << 4) + lc);
                LDSM4(bh0, bh1, bh2, bh3, aw);
                LDSM4(bl0, bl1, bl2, bl3, aw + 2u * (WL - WH));
                MMA16(acc[2 * p],     ah0, ah1, ah2, ah3, bh0, bh2);
                MMA16(acc[2 * p + 1], ah0, ah1, ah2, ah3, bh1, bh3);
                MMA16(acc[2 * p],     ah0, ah1, ah2, ah3, bl0, bl2);
                MMA16(acc[2 * p + 1], ah0, ah1, ah2, ah3, bl1, bl3);
                MMA16(acc[2 * p],     al0, al1, al2, al3, bh0, bh2);
                MMA16(acc[2 * p + 1], al0, al1, al2, al3, bh1, bh3);
            }
        }
    }
    const int tok0 = n0 + (w << 4) + gid;
    #pragma unroll
    for (int nt = 0; nt < 8; nt++) {
        const int c = nt * 8 + 2 * tig;
        float b0s = sbias[c], b1s = sbias[c + 1];
        #pragma unroll
        for (int rr = 0; rr < 2; rr++) {
            float v0 = (acc[nt][2 * rr] + b0s) * scale;
            float v1 = (acc[nt][2 * rr + 1] + b1s) * scale;
            __half h0 = __float2half_rn(v0), h1 = __float2half_rn(v1);
            __half2 hh = __halves2half2(h0, h1);
            __half2 ll = __halves2half2(__float2half_rn(v0 - __half2float(h0)),
                                        __float2half_rn(v1 - __half2float(h1)));
            __half* yp = Y + ((size_t)b * NTOK + tok0 + rr * 8) * 128 + c;
            *(uint32_t*)yp = *(uint32_t*)&hh;
            *(uint32_t*)(yp + 64) = *(uint32_t*)&ll;
        }
    }
}

// ---------------------------------------------------------------------------
// conv v: single-pass fp16 GEMM, output tiled [b][t][o][64j]. m=o.
// ---------------------------------------------------------------------------
__global__ __launch_bounds__(256)
void conv_v_mma(const float* __restrict__ X, const float* __restrict__ W,
                const float* __restrict__ bias, __half* __restrict__ Y, int C) {
    __shared__ __half smc[9472];      // XH[32][136], WH[128][40]
    __shared__ float sbias[128];
    const int WHo = 4352;
    const int b = blockIdx.z, o0 = blockIdx.y << 7, n0 = blockIdx.x << 7;
    const int tid = threadIdx.x, lane = tid & 31, w = tid >> 5;
    const int gid = lane >> 2, tig = lane & 3, lr = lane & 15, lc = (lane >> 4) << 3;
    const uint32_t sb = smem_u32(smc);
    if (tid < 128) sbias[tid] = bias[o0 + tid];
    float acc[16][4];
    #pragma unroll
    for (int i = 0; i < 16; i++)
        #pragma unroll
        for (int e = 0; e < 4; e++) acc[i][e] = 0.f;

    for (int c0 = 0; c0 < C; c0 += 32) {
        __syncthreads();
        #pragma unroll
        for (int p = 0; p < 4; p++) {   // X chunk fp16 (hi only)
            int idx = tid + p * 256, cc = idx >> 5, n4 = (idx & 31) << 2;
            float4 x = *reinterpret_cast<const float4*>(X + ((size_t)b * C + c0 + cc) * NTOK + n0 + n4);
            __half2 p0 = __floats2half2_rn(x.x, x.y), p1 = __floats2half2_rn(x.z, x.w);
            uint2 u; u.x = *(uint32_t*)&p0; u.y = *(uint32_t*)&p1;
            *reinterpret_cast<uint2*>(smc + cc * 136 + n4) = u;
        }
        #pragma unroll
        for (int p = 0; p < 4; p++) {   // W chunk [128o][32c] fp16
            int idx = tid + p * 256, oo = idx >> 3, c4 = (idx & 7) << 2;
            float4 x = *reinterpret_cast<const float4*>(W + (size_t)(o0 + oo) * C + c0 + c4);
            __half2 p0 = __floats2half2_rn(x.x, x.y), p1 = __floats2half2_rn(x.z, x.w);
            uint2 u; u.x = *(uint32_t*)&p0; u.y = *(uint32_t*)&p1;
            *reinterpret_cast<uint2*>(smc + WHo + oo * 40 + c4) = u;
        }
        __syncthreads();
        #pragma unroll
        for (int ks = 0; ks < 2; ks++) {
            uint32_t a0, a1, a2, a3;
            LDSM4(a0, a1, a2, a3, sb + 2u * (WHo + ((w << 4) + lr) * 40 + (ks << 4) + lc));
            #pragma unroll
            for (int tp = 0; tp < 8; tp++) {
                uint32_t v0, v1, v2, v3;
                uint32_t ax = sb + 2u * (((ks << 4) + (lane & 7) + ((lane >> 4) << 3)) * 136
                                         + (tp << 4) + (((lane >> 3) & 1) << 3));
                LDSM4T(v0, v1, v2, v3, ax);
                MMA16(acc[2 * tp],     a0, a1, a2, a3, v0, v2);
                MMA16(acc[2 * tp + 1], a0, a1, a2, a3, v1, v3);
            }
        }
    }
    const int orow = (w << 4) + gid;
    float br0 = sbias[orow], br1 = sbias[orow + 8];
    __half* vbo = Y + ((size_t)b * NT + (n0 >> 6)) * CVCH * 64;
    #pragma unroll
    for (int nt = 0; nt < 16; nt++) {
        int tokoff = nt * 8 + 2 * tig;
        int tadd = tokoff >> 6, j = tokoff & 63;
        __half2 h0 = __floats2half2_rn(acc[nt][0] + br0, acc[nt][1] + br0);
        __half2 h1 = __floats2half2_rn(acc[nt][2] + br1, acc[nt][3] + br1);
        __half* p0 = vbo + ((size_t)tadd * CVCH + o0 + orow) * 64 + j;
        *(uint32_t*)p0 = *(uint32_t*)&h0;
        *(uint32_t*)(p0 + 8 * 64) = *(uint32_t*)&h1;
    }
}

// ---------------------------------------------------------------------------
// Flash attention (R7 structure, ldmatrix fragment loads).
// ---------------------------------------------------------------------------
__global__ __launch_bounds__(512, 1)
void attn_kernel(const float* __restrict__ skip, const float* __restrict__ gamma,
                 float* __restrict__ out) {
    extern __shared__ __align__(16) char sm[];
    __half* smh = (__half*)sm;
    float* smf = (float*)(sm + FOFF);
    const uint32_t sb = smem_u32(sm);
    const int tid = threadIdx.x, lane = tid & 31, w = tid >> 5;
    const int gid = lane >> 2, tig = lane & 3, lr = lane & 15, lc = (lane >> 4) << 3;
    const int r0 = (w & 7) << 4;
    const int ch = w >> 3;
    const int rq = (w & 3) << 5, cq = (w >> 2) << 6;
    const int b = blockIdx.y, i0 = blockIdx.x * TQ;
    const int row0 = r0 + gid, row1 = row0 + 8;

    const __half* qb = g_q16 + (size_t)b * NTOK * 128;
    const __half* kb = g_k16 + (size_t)b * NTOK * 128;
    const __half* vb = g_v16 + (size_t)b * NT * CVCH * TK;

    #pragma unroll
    for (int p = 0; p < 4; p++) {
        int chunk = tid + p * 512, row = chunk >> 4, c16 = chunk & 15;
        uint32_t d = sb + 2u * (c16 < 8 ? SQH + row * 72 + c16 * 8
                                        : SQL + row * 72 + (c16 - 8) * 8);
        CP16(d, qb + (size_t)(i0 + row) * 128 + c16 * 8);
    }
    {
        const int skh = SKB, skl = SKB + 4608, sv = SVB;
        #pragma unroll
        for (int p = 0; p < 2; p++) {
            int chunk = tid + p * 512, row = chunk >> 4, c16 = chunk & 15;
            uint32_t d = sb + 2u * (c16 < 8 ? skh + row * 72 + c16 * 8
                                            : skl + row * 72 + (c16 - 8) * 8);
            CP16(d, kb + (size_t)row * 128 + c16 * 8);
        }
        #pragma unroll
        for (int p = 0; p < 4; p++) {
            int chunk = tid + p * 512, row = chunk >> 3, c8 = chunk & 7;
            CP16(sb + 2u * (sv + row * 72 + c8 * 8), vb + (size_t)row * TK + c8 * 8);
        }
    }
    CPCOMMIT();

    float oacc[16][4];
    #pragma unroll
    for (int t = 0; t < 16; t++)
        #pragma unroll
        for (int e = 0; e < 4; e++) oacc[t][e] = 0.f;
    float rm0 = -1e30f, rm1 = -1e30f, lsum0 = 0.f, lsum1 = 0.f;

    for (int t = 0; t < NT; t++) {
        const int buf = t & 1;
        CPWAIT0();
        __syncthreads();
        if (t + 1 < NT) {
            const int nb2 = buf ^ 1;
            const int skh = SKB + nb2 * 9216, skl = skh + 4608, sv = SVB + nb2 * 18432;
            const size_t j0n = (size_t)(t + 1) * TK;
            #pragma unroll
            for (int p = 0; p < 2; p++) {
                int chunk = tid + p * 512, row = chunk >> 4, c16 = chunk & 15;
                uint32_t d = sb + 2u * (c16 < 8 ? skh + row * 72 + c16 * 8
                                                : skl + row * 72 + (c16 - 8) * 8);
                CP16(d, kb + (j0n + row) * 128 + c16 * 8);
            }
            const __half* vt = vb + (size_t)(t + 1) * CVCH * TK;
            #pragma unroll
            for (int p = 0; p < 4; p++) {
                int chunk = tid + p * 512, row = chunk >> 3, c8 = chunk & 7;
                CP16(sb + 2u * (sv + row * 72 + c8 * 8), vt + (size_t)row * TK + c8 * 8);
            }
        }
        CPCOMMIT();

        const int kh = SKB + buf * 9216;
        float sacc[4][4];
        #pragma unroll
        for (int tt = 0; tt < 4; tt++)
            #pragma unroll
            for (int e = 0; e < 4; e++) sacc[tt][e] = 0.f;
        #pragma unroll
        for (int kk = 0; kk < 4; kk++) {
            uint32_t ah0, ah1, ah2, ah3, al0, al1, al2, al3;
            uint32_t aq = sb + 2u * (SQH + (r0 + lr) * 72 + kk * 16 + lc);
            LDSM4(ah0, ah1, ah2, ah3, aq);
            LDSM4(al0, al1, al2, al3, aq + 2u * SQL);
            #pragma unroll
            for (int tp = 0; tp < 2; tp++) {
                uint32_t bh0, bh1, bh2, bh3, bl0, bl1, bl2, bl3;
                uint32_t ak = sb + 2u * (kh + (ch * 32 + tp * 16 + lr) * 72 + kk * 16 + lc);
                LDSM4(bh0, bh1, bh2, bh3, ak);
                LDSM4(bl0, bl1, bl2, bl3, ak + 2u * 4608);
                MMA16(sacc[2 * tp],     ah0, ah1, ah2, ah3, bh0, bh2);
                MMA16(sacc[2 * tp + 1], ah0, ah1, ah2, ah3, bh1, bh3);
                MMA16(sacc[2 * tp],     ah0, ah1, ah2, ah3, bl0, bl2);
                MMA16(sacc[2 * tp + 1], ah0, ah1, ah2, ah3, bl1, bl3);
                MMA16(sacc[2 * tp],     al0, al1, al2, al3, bh0, bh2);
                MMA16(sacc[2 * tp + 1], al0, al1, al2, al3, bh1, bh3);
            }
        }
        float mx0 = -1e30f, mx1 = -1e30f;
        #pragma unroll
        for (int tt = 0; tt < 4; tt++) {
            mx0 = fmaxf(mx0, fmaxf(sacc[tt][0], sacc[tt][1]));
            mx1 = fmaxf(mx1, fmaxf(sacc[tt][2], sacc[tt][3]));
        }
        mx0 = fmaxf(mx0, __shfl_xor_sync(0xFFFFFFFFu, mx0, 1));
        mx0 = fmaxf(mx0, __shfl_xor_sync(0xFFFFFFFFu, mx0, 2));
        mx1 = fmaxf(mx1, __shfl_xor_sync(0xFFFFFFFFu, mx1, 1));
        mx1 = fmaxf(mx1, __shfl_xor_sync(0xFFFFFFFFu, mx1, 2));
        if (tig == 0) {
            smf[RM + row0 * 2 + ch] = mx0;
            smf[RM + row1 * 2 + ch] = mx1;
        }
        __syncthreads();

        float mn0 = fmaxf(rm0, fmaxf(smf[RM + row0 * 2], smf[RM + row0 * 2 + 1]));
        float mn1 = fmaxf(rm1, fmaxf(smf[RM + row1 * 2], smf[RM + row1 * 2 + 1]));
        float f0 = fast_exp2(rm0 - mn0), f1 = fast_exp2(rm1 - mn1);
        rm0 = mn0; rm1 = mn1;
        if (tig == 0 && ch == 0) { smf[FF + row0] = f0; smf[FF + row1] = f1; }
        float ps0 = 0.f, ps1 = 0.f;
        #pragma unroll
        for (int tt = 0; tt < 4; tt++) {
            float p00 = fast_exp2(sacc[tt][0] - mn0);
            float p01 = fast_exp2(sacc[tt][1] - mn0);
            float p10 = fast_exp2(sacc[tt][2] - mn1);
            float p11 = fast_exp2(sacc[tt][3] - mn1);
            ps0 += p00 + p01; ps1 += p10 + p11;
            __half2 h0 = __floats2half2_rn(p00, p01);
            __half2 h1 = __floats2half2_rn(p10, p11);
            const int cc = ch * 32 + tt * 8 + 2 * tig;
            *(uint32_t*)(smh + SP + row0 * 72 + cc) = *(uint32_t*)&h0;
            *(uint32_t*)(smh + SP + row1 * 72 + cc) = *(uint32_t*)&h1;
        }
        lsum0 = lsum0 * f0 + ps0;
        lsum1 = lsum1 * f1 + ps1;
        __syncthreads();

        const int sv = SVB + buf * 18432;
        float fa0 = smf[FF + rq + gid],      fa1 = smf[FF + rq + gid + 8];
        float fb0 = smf[FF + rq + 16 + gid], fb1 = smf[FF + rq + 16 + gid + 8];
        #pragma unroll
        for (int nt = 0; nt < 8; nt++) {
            oacc[nt][0] *= fa0; oacc[nt][1] *= fa0;
            oacc[nt][2] *= fa1; oacc[nt][3] *= fa1;
            oacc[8 + nt][0] *= fb0; oacc[8 + nt][1] *= fb0;
            oacc[8 + nt][2] *= fb1; oacc[8 + nt][3] *= fb1;
        }
        #pragma unroll
        for (int kk = 0; kk < 4; kk++) {
            uint32_t pa0, pa1, pa2, pa3, qa0, qa1, qa2, qa3;
            uint32_t ap = sb + 2u * (SP + (rq + lr) * 72 + kk * 16 + lc);
            LDSM4(pa0, pa1, pa2, pa3, ap);
            LDSM4(qa0, qa1, qa2, qa3, ap + 2u * (16 * 72));
            #pragma unroll
            for (int np = 0; np < 4; np++) {
                uint32_t v0, v1, v2, v3;
                LDSM4(v0, v1, v2, v3,
                      sb + 2u * (sv + (cq + np * 16 + lr) * 72 + kk * 16 + lc));
                MMA16(oacc[2 * np],         pa0, pa1, pa2, pa3, v0, v2);
                MMA16(oacc[2 * np + 1],     pa0, pa1, pa2, pa3, v1, v3);
                MMA16(oacc[8 + 2 * np],     qa0, qa1, qa2, qa3, v0, v2);
                MMA16(oacc[8 + 2 * np + 1], qa0, qa1, qa2, qa3, v1, v3);
            }
        }
    }

    lsum0 += __shfl_xor_sync(0xFFFFFFFFu, lsum0, 1);
    lsum0 += __shfl_xor_sync(0xFFFFFFFFu, lsum0, 2);
    lsum1 += __shfl_xor_sync(0xFFFFFFFFu, lsum1, 1);
    lsum1 += __shfl_xor_sync(0xFFFFFFFFu, lsum1, 2);
    if (tig == 0) {
        smf[LR + row0 * 2 + ch] = lsum0;
        smf[LR + row1 * 2 + ch] = lsum1;
    }
    __syncthreads();

    const float gm = __ldg(gamma);
    const float* skb = skip + (size_t)b * CVCH * NTOK;
    float* ob = out + (size_t)b * CVCH * NTOK;
    #pragma unroll
    for (int mt = 0; mt < 2; mt++) {
        const int ra = rq + mt * 16 + gid, rb = ra + 8;
        const float fca = gm / (smf[LR + ra * 2] + smf[LR + ra * 2 + 1]);
        const float fcb = gm / (smf[LR + rb * 2] + smf[LR + rb * 2 + 1]);
        const int ia = i0 + ra, ib = i0 + rb;
        #pragma unroll
        for (int nt = 0; nt < 8; nt++) {
            const int c = cq + nt * 8 + 2 * tig;
            const size_t oA = (size_t)c * NTOK, oB = (size_t)(c + 1) * NTOK;
            const float* acc = oacc[mt * 8 + nt];
            ob[oA + ia] = acc[0] * fca + skb[oA + ia];
            ob[oB + ia] = acc[1] * fca + skb[oB + ia];
            ob[oA + ib] = acc[2] * fcb + skb[oA + ib];
            ob[oB + ib] = acc[3] * fcb + skb[oB + ib];
        }
    }
}

// ---------------------------------------------------------------------------
static __half* s_q = nullptr;
static __half* s_k = nullptr;
static __half* s_v = nullptr;

extern "C" void kernel_launch(void* const* d_in, const int* in_sizes, int n_in,
                              void* d_out, int out_size) {
    (void)in_sizes; (void)n_in; (void)out_size;
    static bool initialized = []() {
        void* p;
        cudaGetSymbolAddress(&p, g_q16); s_q = (__half*)p;
        cudaGetSymbolAddress(&p, g_k16); s_k = (__half*)p;
        cudaGetSymbolAddress(&p, g_v16); s_v = (__half*)p;
        cudaFuncSetAttribute(attn_kernel, cudaFuncAttributeMaxDynamicSharedMemorySize,
                             ATTN_SMEM);
        return true;
    }();
    (void)initialized;

    const float* gate  = (const float*)d_in[0];
    const float* skip  = (const float*)d_in[1];
    const float* Wq    = (const float*)d_in[2];
    const float* bq    = (const float*)d_in[3];
    const float* Wk    = (const float*)d_in[4];
    const float* bk    = (const float*)d_in[5];
    const float* Wv    = (const float*)d_in[6];
    const float* bv    = (const float*)d_in[7];
    const float* gamma = (const float*)d_in[8];
    float* out = (float*)d_out;

    const float LOG2E = 1.4426950408889634f;

    conv_qk_mma<<<dim3(32, 1, NB), 256>>>(gate, Wq, bq, s_q, 512, LOG2E);
    conv_qk_mma<<<dim3(32, 1, NB), 256>>>(skip, Wk, bk, s_k, 256, 1.0f);
    conv_v_mma <<<dim3(32, 2, NB), 256>>>(skip, Wv, bv, s_v, 256);
    attn_kernel<<<dim3(NTOK / TQ, NB), 512, ATTN_SMEM>>>(skip, gamma, out);
}